// round 6
// baseline (speedup 1.0000x reference)
#include <cuda_runtime.h>

#define J    24
#define TPB  128
#define EPB  256          // elements per block (2 per thread)
#define PITCH 39          // staging row pitch (odd -> conflict-free)

typedef unsigned long long u64;

// Per-joint constants, each duplicated into both f32x2 lanes:
// [0..11]=T_origin rows 0..2, [12..14]=ux,uy,uz, [15..17]=uxx,uyy,uzz,
// [18..20]=uxy,uxz,uyz.
__constant__ float2 cPk[J * 21];
__device__ float2 g_pk[J * 21];   // scratch filled by prep kernel

__global__ void fk_prep(const float* __restrict__ Torg,
                        const float* __restrict__ axes) {
    int j = threadIdx.x;
    if (j < J) {
        const float* p = Torg + j * 16;
        #pragma unroll
        for (int k = 0; k < 12; ++k) g_pk[j*21 + k] = make_float2(p[k], p[k]);
        float ux = axes[j*3+0], uy = axes[j*3+1], uz = axes[j*3+2];
        g_pk[j*21+12] = make_float2(ux, ux);
        g_pk[j*21+13] = make_float2(uy, uy);
        g_pk[j*21+14] = make_float2(uz, uz);
        g_pk[j*21+15] = make_float2(ux*ux, ux*ux);
        g_pk[j*21+16] = make_float2(uy*uy, uy*uy);
        g_pk[j*21+17] = make_float2(uz*uz, uz*uz);
        g_pk[j*21+18] = make_float2(ux*uy, ux*uy);
        g_pk[j*21+19] = make_float2(ux*uz, ux*uz);
        g_pk[j*21+20] = make_float2(uy*uz, uy*uz);
    }
}

__device__ __forceinline__ u64 pk2(float lo, float hi) {
    u64 r; asm("mov.b64 %0, {%1, %2};" : "=l"(r) : "f"(lo), "f"(hi)); return r;
}
__device__ __forceinline__ void upk2(u64 v, float& lo, float& hi) {
    asm("mov.b64 {%0, %1}, %2;" : "=f"(lo), "=f"(hi) : "l"(v));
}
__device__ __forceinline__ u64 f2(u64 a, u64 b, u64 c) {   // a*b + c (both lanes)
    u64 d; asm("fma.rn.f32x2 %0, %1, %2, %3;" : "=l"(d) : "l"(a), "l"(b), "l"(c));
    return d;
}
__device__ __forceinline__ u64 m2(u64 a, u64 b) {          // a*b (both lanes)
    u64 d; asm("mul.rn.f32x2 %0, %1, %2;" : "=l"(d) : "l"(a), "l"(b));
    return d;
}

#define ONE2 0x3F8000003F800000ULL   // {1.0f, 1.0f}
#define NEG2 0xBF800000BF800000ULL   // {-1.0f, -1.0f}

__global__ __launch_bounds__(TPB, 4) void fk_kernel(
    const float* __restrict__ angles,   // [B, 24]
    float* __restrict__ out,            // [B, 75]
    int B)
{
    // Column-chunked staging: chunk 0 = output cols [0,39), chunk 1 = [39,75)
    // (36 cols, stored at local cols [0,36)). Row = local element index.
    __shared__ float sbuf[EPB * PITCH];   // 39936 B

    const int tid  = threadIdx.x;
    const int base = blockIdx.x * EPB;
    const int e0 = base + tid;        // row tid
    const int e1 = e0 + TPB;          // row tid + 128
    const bool v0 = (e0 < B), v1 = (e1 < B);
    const float4* ap0 = reinterpret_cast<const float4*>(angles + (size_t)e0 * J);
    const float4* ap1 = reinterpret_cast<const float4*>(angles + (size_t)e1 * J);

    const int nvalid = min(EPB, B - base);
    float* gout = out + (size_t)base * 75;

    // Packed chain transform M (3x4), identity.
    u64 M[12];
    #pragma unroll
    for (int k = 0; k < 12; ++k) M[k] = 0ULL;
    M[0] = ONE2; M[5] = ONE2; M[10] = ONE2;

    // base_pos zeros (chunk 0, cols 0..2)
    if (v0) { sbuf[tid*PITCH+0]=0.f; sbuf[tid*PITCH+1]=0.f; sbuf[tid*PITCH+2]=0.f; }
    if (v1) { sbuf[(tid+TPB)*PITCH+0]=0.f; sbuf[(tid+TPB)*PITCH+1]=0.f; sbuf[(tid+TPB)*PITCH+2]=0.f; }

    #pragma unroll
    for (int half = 0; half < 2; ++half) {
        #pragma unroll
        for (int seg = 0; seg < 3; ++seg) {
            // 4 joints' angles for both elements (2x LDG.128).
            float4 w0 = v0 ? __ldg(ap0 + half*3 + seg) : make_float4(0,0,0,0);
            float4 w1 = v1 ? __ldg(ap1 + half*3 + seg) : make_float4(0,0,0,0);
            float A0[4] = {w0.x, w0.y, w0.z, w0.w};
            float A1[4] = {w1.x, w1.y, w1.z, w1.w};

            #pragma unroll
            for (int q = 0; q < 4; ++q) {
                const int j = half*12 + seg*4 + q;
                const u64* C = reinterpret_cast<const u64*>(cPk + j*21);

                float s0, c0, s1, c1;
                __sincosf(A0[q], &s0, &c0);
                __sincosf(A1[q], &s1, &c1);
                const u64 S  = pk2(s0, s1);
                const u64 Cc = pk2(c0, c1);
                const u64 OC = f2(Cc, NEG2, ONE2);   // 1 - cos
                const u64 SN = m2(S, NEG2);          // -sin

                // Rodrigues R (packed), via precomputed axis products.
                const u64 r00 = f2(OC, C[15], Cc);
                const u64 r11 = f2(OC, C[16], Cc);
                const u64 r22 = f2(OC, C[17], Cc);
                const u64 oxy = m2(OC, C[18]);
                const u64 oxz = m2(OC, C[19]);
                const u64 oyz = m2(OC, C[20]);
                const u64 r01 = f2(SN, C[14], oxy), r10 = f2(S,  C[14], oxy);
                const u64 r02 = f2(S,  C[13], oxz), r20 = f2(SN, C[13], oxz);
                const u64 r12 = f2(SN, C[12], oyz), r21 = f2(S,  C[12], oyz);

                // G = M * T_origin (affine)
                u64 G[12];
                #pragma unroll
                for (int r = 0; r < 3; ++r) {
                    const u64 a = M[r*4+0], b = M[r*4+1], c = M[r*4+2], d = M[r*4+3];
                    G[r*4+0] = f2(c, C[8],  f2(b, C[4], m2(a, C[0])));
                    G[r*4+1] = f2(c, C[9],  f2(b, C[5], m2(a, C[1])));
                    G[r*4+2] = f2(c, C[10], f2(b, C[6], m2(a, C[2])));
                    G[r*4+3] = f2(a, C[3],  f2(b, C[7], f2(c, C[11], d)));
                }
                // M = G * Rj (rotation-only)
                #pragma unroll
                for (int r = 0; r < 3; ++r) {
                    const u64 a = G[r*4+0], b = G[r*4+1], c = G[r*4+2];
                    M[r*4+0] = f2(c, r20, f2(b, r10, m2(a, r00)));
                    M[r*4+1] = f2(c, r21, f2(b, r11, m2(a, r01)));
                    M[r*4+2] = f2(c, r22, f2(b, r12, m2(a, r02)));
                    M[r*4+3] = G[r*4+3];
                }

                // Stage positions (chunk-local column, compile-time).
                const int cc = (half == 0) ? (3 + 3*j) : (3*(j - 12));
                float x0, x1, y0, y1, z0, z1;
                upk2(M[3],  x0, x1);
                upk2(M[7],  y0, y1);
                upk2(M[11], z0, z1);
                if (v0) {
                    float* s = sbuf + tid*PITCH + cc;
                    s[0] = x0; s[1] = y0; s[2] = z0;
                }
                if (v1) {
                    float* s = sbuf + (tid+TPB)*PITCH + cc;
                    s[0] = x1; s[1] = y1; s[2] = z1;
                }
            }
        }

        __syncthreads();  // chunk fully staged

        if (half == 0) {  // flush cols [0,39)
            const unsigned cnt = (unsigned)nvalid * 39u;
            for (unsigned i = tid; i < cnt; i += TPB) {
                const unsigned r = i / 39u, c = i - r * 39u;
                gout[r*75u + c] = sbuf[r*PITCH + c];
            }
            __syncthreads();  // buffer reusable
        } else {          // flush cols [39,75)
            const unsigned cnt = (unsigned)nvalid * 36u;
            for (unsigned i = tid; i < cnt; i += TPB) {
                const unsigned r = i / 36u, c = i - r * 36u;
                gout[r*75u + 39u + c] = sbuf[r*PITCH + c];
            }
        }
    }
}

extern "C" void kernel_launch(void* const* d_in, const int* in_sizes, int n_in,
                              void* d_out, int out_size) {
    const float* angles = (const float*)d_in[0];   // [B, 24]
    const float* Torg   = (const float*)d_in[1];   // [24, 4, 4]
    const float* axes   = (const float*)d_in[2];   // [24, 3]
    float* out = (float*)d_out;                    // [B, 75]

    // Build duplicated packed constants, then D2D into the constant bank.
    fk_prep<<<1, 32>>>(Torg, axes);
    void* src = nullptr;
    cudaGetSymbolAddress(&src, g_pk);
    cudaMemcpyToSymbolAsync(cPk, src, J * 21 * sizeof(float2), 0,
                            cudaMemcpyDeviceToDevice);

    const int B = in_sizes[0] / J;
    const int blocks = (B + EPB - 1) / EPB;
    fk_kernel<<<blocks, TPB>>>(angles, out, B);
}

// round 7
// speedup vs baseline: 1.2564x; 1.2564x over previous
#include <cuda_runtime.h>

#define J    24
#define TPB  128

__global__ __launch_bounds__(TPB, 8) void fk_kernel(
    const float* __restrict__ angles,   // [B, 24]
    const float* __restrict__ Torg,     // [24, 4, 4]
    const float* __restrict__ axes,     // [24, 3] unit axes
    float* __restrict__ out,            // [B, 75]
    int B)
{
    // Per-joint derived constants: {wx,wy,wz,_, bx,by,bz,_}
    __shared__ __align__(16) float kjc[J][8];
    // Warp-private double-buffered output staging:
    // output col c -> buffer (c/25)&1, local col c%25, row = lane.
    // Pitch 25 (odd) -> conflict-free.
    __shared__ float sbuf[2][4][32][25];

    const int tid  = threadIdx.x;
    const int warp = tid >> 5;
    const int lane = tid & 31;

    // ---- Warp 0: shuffle-scan of cumulative fixed rotations ----
    // C_j = Q_0 * ... * Q_j ;  w_j = C_j u_j ;  b_j = C_{j-1} a_j.
    if (warp == 0) {
        float m[9];                      // 3x3, row-major; lanes >= J hold I
        float ax = 0.f, ay = 0.f, az = 0.f;
        float ux = 0.f, uy = 0.f, uz = 0.f;
        m[0] = 1.f; m[1] = 0.f; m[2] = 0.f;
        m[3] = 0.f; m[4] = 1.f; m[5] = 0.f;
        m[6] = 0.f; m[7] = 0.f; m[8] = 1.f;
        if (lane < J) {
            const float* t = Torg + lane * 16;
            m[0]=t[0]; m[1]=t[1]; m[2]=t[2];   ax=t[3];
            m[3]=t[4]; m[4]=t[5]; m[5]=t[6];   ay=t[7];
            m[6]=t[8]; m[7]=t[9]; m[8]=t[10];  az=t[11];
            ux = axes[lane*3+0]; uy = axes[lane*3+1]; uz = axes[lane*3+2];
        }
        // Inclusive Kogge-Stone: m_lane <- C_lane
        #pragma unroll
        for (int d = 1; d < J; d <<= 1) {
            float L[9];
            #pragma unroll
            for (int k = 0; k < 9; ++k)
                L[k] = __shfl_up_sync(0xffffffffu, m[k], d);
            if (lane >= d) {
                float n[9];
                #pragma unroll
                for (int r = 0; r < 3; ++r)
                    #pragma unroll
                    for (int c = 0; c < 3; ++c)
                        n[r*3+c] = L[r*3+0]*m[0*3+c] + L[r*3+1]*m[1*3+c]
                                 + L[r*3+2]*m[2*3+c];
                #pragma unroll
                for (int k = 0; k < 9; ++k) m[k] = n[k];
            }
        }
        // Exclusive prefix C_{lane-1} (identity at lane 0)
        float E[9];
        #pragma unroll
        for (int k = 0; k < 9; ++k)
            E[k] = __shfl_up_sync(0xffffffffu, m[k], 1);
        if (lane == 0) {
            E[0]=1.f; E[1]=0.f; E[2]=0.f;
            E[3]=0.f; E[4]=1.f; E[5]=0.f;
            E[6]=0.f; E[7]=0.f; E[8]=1.f;
        }
        if (lane < J) {
            kjc[lane][0] = m[0]*ux + m[1]*uy + m[2]*uz;   // w = C_j u
            kjc[lane][1] = m[3]*ux + m[4]*uy + m[5]*uz;
            kjc[lane][2] = m[6]*ux + m[7]*uy + m[8]*uz;
            kjc[lane][3] = 0.f;
            kjc[lane][4] = E[0]*ax + E[1]*ay + E[2]*az;   // b = C_{j-1} a
            kjc[lane][5] = E[3]*ax + E[4]*ay + E[5]*az;
            kjc[lane][6] = E[6]*ax + E[7]*ay + E[8]*az;
            kjc[lane][7] = 0.f;
        }
    }
    __syncthreads();

    const int base = blockIdx.x * TPB;
    const int e = base + tid;
    const bool active = (e < B);
    const int nvalid = min(TPB, B - base);
    const float4* ap = reinterpret_cast<const float4*>(angles + (size_t)e * J);
    float* gout = out + (size_t)base * 75;

    // Running state: quaternion P (Hamilton, w,x,y,z) and position p.
    float Pw = 1.f, Px = 0.f, Py = 0.f, Pz = 0.f;
    float px = 0.f, py = 0.f, pz = 0.f;

    float* rowA = &sbuf[0][warp][lane][0];
    float* rowB = &sbuf[1][warp][lane][0];

    // base_pos -> cols 0..2 (buffer A)
    rowA[0] = 0.f; rowA[1] = 0.f; rowA[2] = 0.f;

    const int wrows = min(32, max(0, nvalid - warp * 32));
    const float4* kc = reinterpret_cast<const float4*>(kjc);

    #pragma unroll
    for (int seg = 0; seg < 3; ++seg) {
        float a[8];
        {
            float4 v0 = active ? __ldg(ap + 2*seg)     : make_float4(0,0,0,0);
            float4 v1 = active ? __ldg(ap + 2*seg + 1) : make_float4(0,0,0,0);
            a[0]=v0.x; a[1]=v0.y; a[2]=v0.z; a[3]=v0.w;
            a[4]=v1.x; a[5]=v1.y; a[6]=v1.z; a[7]=v1.w;
        }
        #pragma unroll
        for (int q = 0; q < 8; ++q) {
            const int j = seg * 8 + q;
            const float4 wv = kc[2*j];       // w_j
            const float4 bv = kc[2*j + 1];   // b_j

            // p += rot(P, b):  t = qv x b;  p += b + 2*Pw*t + 2*(qv x t)
            const float tx = Py*bv.z - Pz*bv.y;
            const float ty = Pz*bv.x - Px*bv.z;
            const float tz = Px*bv.y - Py*bv.x;
            const float w2 = Pw + Pw;
            const float ox = Py*tz - Pz*ty;
            const float oy = Pz*tx - Px*tz;
            const float oz = Px*ty - Py*tx;
            px += bv.x + w2*tx + 2.f*ox;
            py += bv.y + w2*ty + 2.f*oy;
            pz += bv.z + w2*tz + 2.f*oz;

            // Stage position (compile-time column mapping).
            {
                const int c0 = 3 + 3*j;
                float* d0 = (((c0+0)/25)&1) ? rowB : rowA;
                float* d1 = (((c0+1)/25)&1) ? rowB : rowA;
                float* d2 = (((c0+2)/25)&1) ? rowB : rowA;
                d0[(c0+0)%25] = px;
                d1[(c0+1)%25] = py;
                d2[(c0+2)%25] = pz;
            }

            // P <- P (x) (cos h, sin h * w)   [skip after last joint]
            if (j < J - 1) {
                float s, co;
                __sincosf(0.5f * a[q], &s, &co);
                const float qx = s*wv.x, qy = s*wv.y, qz = s*wv.z;
                const float nw = Pw*co - Px*qx - Py*qy - Pz*qz;
                const float nx = Pw*qx + Px*co + Py*qz - Pz*qy;
                const float ny = Pw*qy - Px*qz + Py*co + Pz*qx;
                const float nz = Pw*qz + Px*qy - Py*qx + Pz*co;
                Pw = nw; Px = nx; Py = ny; Pz = nz;
            }
        }

        // Flush chunk `seg` (cols [25*seg, 25*seg+25)), buffer seg&1.
        __syncwarp();
        if (wrows > 0) {
            const float* src = &sbuf[seg & 1][warp][0][0];
            float* dst = gout + (size_t)(warp*32) * 75 + seg*25;
            const int cnt = wrows * 25;
            #pragma unroll 5
            for (int i = lane; i < cnt; i += 32) {
                const int r = i / 25;
                const int c = i - r * 25;
                dst[r*75 + c] = src[r*25 + c];
            }
        }
        __syncwarp();
    }
}

extern "C" void kernel_launch(void* const* d_in, const int* in_sizes, int n_in,
                              void* d_out, int out_size) {
    const float* angles = (const float*)d_in[0];   // [B, 24]
    const float* Torg   = (const float*)d_in[1];   // [24, 4, 4]
    const float* axes   = (const float*)d_in[2];   // [24, 3]
    float* out = (float*)d_out;                    // [B, 75]

    const int B = in_sizes[0] / J;
    const int blocks = (B + TPB - 1) / TPB;
    fk_kernel<<<blocks, TPB>>>(angles, Torg, axes, out, B);
}

// round 8
// speedup vs baseline: 1.4962x; 1.1908x over previous
#include <cuda_runtime.h>

#define J    24
#define TPB  128

__global__ __launch_bounds__(TPB) void fk_kernel(
    const float* __restrict__ angles,   // [B, 24]
    const float* __restrict__ Torg,     // [24, 4, 4]
    const float* __restrict__ axes,     // [24, 3] unit axes
    float* __restrict__ out,            // [B, 75]
    int B)
{
    // Per-joint derived constants: {wx,wy,wz,_, bx,by,bz,_}
    __shared__ __align__(16) float kjc[J][8];
    // Full output staging: thread t owns s_out[t*75 .. t*75+74].
    // Stride 75 odd -> bank-conflict-free; flushed once with float4.
    __shared__ __align__(16) float s_out[TPB * 75];

    const int tid  = threadIdx.x;
    const int warp = tid >> 5;
    const int lane = tid & 31;

    // ---- Warp 0: shuffle-scan of cumulative fixed rotations ----
    // C_j = Q_0 ... Q_j ;  w_j = C_j u_j ;  b_j = C_{j-1} t_j.
    if (warp == 0) {
        float m[9];
        float ax = 0.f, ay = 0.f, az = 0.f;
        float ux = 0.f, uy = 0.f, uz = 0.f;
        m[0]=1.f; m[1]=0.f; m[2]=0.f;
        m[3]=0.f; m[4]=1.f; m[5]=0.f;
        m[6]=0.f; m[7]=0.f; m[8]=1.f;
        if (lane < J) {
            const float* t = Torg + lane * 16;
            m[0]=t[0]; m[1]=t[1]; m[2]=t[2];   ax=t[3];
            m[3]=t[4]; m[4]=t[5]; m[5]=t[6];   ay=t[7];
            m[6]=t[8]; m[7]=t[9]; m[8]=t[10];  az=t[11];
            ux = axes[lane*3+0]; uy = axes[lane*3+1]; uz = axes[lane*3+2];
        }
        #pragma unroll
        for (int d = 1; d < J; d <<= 1) {          // inclusive Kogge-Stone
            float L[9];
            #pragma unroll
            for (int k = 0; k < 9; ++k)
                L[k] = __shfl_up_sync(0xffffffffu, m[k], d);
            if (lane >= d) {
                float n[9];
                #pragma unroll
                for (int r = 0; r < 3; ++r)
                    #pragma unroll
                    for (int c = 0; c < 3; ++c)
                        n[r*3+c] = L[r*3+0]*m[0*3+c] + L[r*3+1]*m[1*3+c]
                                 + L[r*3+2]*m[2*3+c];
                #pragma unroll
                for (int k = 0; k < 9; ++k) m[k] = n[k];
            }
        }
        float E[9];                                 // exclusive prefix
        #pragma unroll
        for (int k = 0; k < 9; ++k)
            E[k] = __shfl_up_sync(0xffffffffu, m[k], 1);
        if (lane == 0) {
            E[0]=1.f; E[1]=0.f; E[2]=0.f;
            E[3]=0.f; E[4]=1.f; E[5]=0.f;
            E[6]=0.f; E[7]=0.f; E[8]=1.f;
        }
        if (lane < J) {
            kjc[lane][0] = m[0]*ux + m[1]*uy + m[2]*uz;   // w = C_j u
            kjc[lane][1] = m[3]*ux + m[4]*uy + m[5]*uz;
            kjc[lane][2] = m[6]*ux + m[7]*uy + m[8]*uz;
            kjc[lane][3] = 0.f;
            kjc[lane][4] = E[0]*ax + E[1]*ay + E[2]*az;   // b = C_{j-1} t
            kjc[lane][5] = E[3]*ax + E[4]*ay + E[5]*az;
            kjc[lane][6] = E[6]*ax + E[7]*ay + E[8]*az;
            kjc[lane][7] = 0.f;
        }
    }

    const int base = blockIdx.x * TPB;
    const int e = base + tid;
    const bool active = (e < B);

    // All 24 angles up front: 6 LDG.128 (row start b*96 B is 16B aligned).
    float a[J];
    if (active) {
        const float4* ap = reinterpret_cast<const float4*>(angles + (size_t)e * J);
        #pragma unroll
        for (int q = 0; q < J / 4; ++q) {
            float4 v = __ldg(ap + q);
            a[4*q+0] = v.x; a[4*q+1] = v.y; a[4*q+2] = v.z; a[4*q+3] = v.w;
        }
    }

    __syncthreads();   // kjc ready

    if (active) {
        // State: quaternion P (w,x,y,z) and position p.
        float Pw = 1.f, Px = 0.f, Py = 0.f, Pz = 0.f;
        float px = 0.f, py = 0.f, pz = 0.f;

        float* so = s_out + tid * 75;
        so[0] = 0.f; so[1] = 0.f; so[2] = 0.f;   // base_pos

        const float4* kc = reinterpret_cast<const float4*>(kjc);

        #pragma unroll
        for (int j = 0; j < J; ++j) {
            const float4 wv = kc[2*j];       // w_j
            const float4 bv = kc[2*j + 1];   // b_j

            // p += rot(P, b):  t = qv x b;  p += b + 2*Pw*t + 2*(qv x t)
            const float tx = Py*bv.z - Pz*bv.y;
            const float ty = Pz*bv.x - Px*bv.z;
            const float tz = Px*bv.y - Py*bv.x;
            const float w2 = Pw + Pw;
            const float ox = Py*tz - Pz*ty;
            const float oy = Pz*tx - Px*tz;
            const float oz = Px*ty - Py*tx;
            px += bv.x + w2*tx + 2.f*ox;
            py += bv.y + w2*ty + 2.f*oy;
            pz += bv.z + w2*tz + 2.f*oz;

            so[3 + 3*j + 0] = px;
            so[3 + 3*j + 1] = py;
            so[3 + 3*j + 2] = pz;

            // P <- P (x) (cos h, sin h * w)   [skip after last joint]
            if (j < J - 1) {
                float s, co;
                __sincosf(0.5f * a[j], &s, &co);
                const float qx = s*wv.x, qy = s*wv.y, qz = s*wv.z;
                const float nw = Pw*co - Px*qx - Py*qy - Pz*qz;
                const float nx = Pw*qx + Px*co + Py*qz - Pz*qy;
                const float ny = Pw*qy - Px*qz + Py*co + Pz*qx;
                const float nz = Pw*qz + Px*qy - Py*qx + Pz*co;
                Pw = nw; Px = nx; Py = ny; Pz = nz;
            }
        }
    }

    __syncthreads();   // s_out fully staged

    // Single fully-coalesced float4 flush of the [TPB, 75] slab.
    const int nvalid = min(TPB, B - base);
    float* gout = out + (size_t)base * 75;
    if (nvalid == TPB) {
        const float4* sv = reinterpret_cast<const float4*>(s_out);
        float4* gv = reinterpret_cast<float4*>(gout);
        #pragma unroll 5
        for (int i = tid; i < TPB * 75 / 4; i += TPB) gv[i] = sv[i];
    } else if (nvalid > 0) {
        const int cnt = nvalid * 75;
        for (int i = tid; i < cnt; i += TPB) gout[i] = s_out[i];
    }
}

extern "C" void kernel_launch(void* const* d_in, const int* in_sizes, int n_in,
                              void* d_out, int out_size) {
    const float* angles = (const float*)d_in[0];   // [B, 24]
    const float* Torg   = (const float*)d_in[1];   // [24, 4, 4]
    const float* axes   = (const float*)d_in[2];   // [24, 3]
    float* out = (float*)d_out;                    // [B, 75]

    const int B = in_sizes[0] / J;
    const int blocks = (B + TPB - 1) / TPB;
    fk_kernel<<<blocks, TPB>>>(angles, Torg, axes, out, B);
}